// round 3
// baseline (speedup 1.0000x reference)
#include <cuda_runtime.h>

#define L       64
#define L4      16
#define CHUNK   64
#define TPB     128
#define MAXQ    2048
#define MAXCH   32

// ---- scratch ( __device__ globals: allocation-free ) ----
__device__ float g_A[MAXQ * L];                 // per-query MLP affine part (incl. b1)
__device__ float g_B[MAXQ * L];                 // per-obs   MLP affine part
__device__ float g_V[MAXQ * L];                 // value-projected h_obs
__device__ float g_psum[MAXCH * MAXQ];          // partial sum of weights
__device__ float g_pacc[MAXCH * MAXQ * L];      // partial weighted value sums

// ------------------------------------------------------------------
// Precompute A, B, V.
//   A[q,l] = b1[l] + sum_d pos_q[q,d]*(W1[d,l] + W1[6+d,l])
//   B[o,l] =         sum_d pos_o[o,d]*(W1[3+d,l] - W1[6+d,l])
//   V[o,l] = bv[l] + sum_k h_obs[o,k]*Wv[k,l]
// ------------------------------------------------------------------
__global__ void prep_ABV(const float* __restrict__ pos_q,
                         const float* __restrict__ pos_o,
                         const float* __restrict__ h_obs,
                         const float* __restrict__ W1,
                         const float* __restrict__ b1,
                         const float* __restrict__ Wv,
                         const float* __restrict__ bv,
                         int NQ, int NO)
{
    int idx = blockIdx.x * blockDim.x + threadIdx.x;
    if (idx < NQ * L) {
        int q = idx >> 6, l = idx & 63;
        float px = pos_q[q*3+0], py = pos_q[q*3+1], pz = pos_q[q*3+2];
        float a = b1[l];
        a = fmaf(px, W1[0*L+l] + W1[6*L+l], a);
        a = fmaf(py, W1[1*L+l] + W1[7*L+l], a);
        a = fmaf(pz, W1[2*L+l] + W1[8*L+l], a);
        g_A[idx] = a;
        return;
    }
    idx -= NQ * L;
    if (idx < NO * L) {
        int o = idx >> 6, l = idx & 63;
        float px = pos_o[o*3+0], py = pos_o[o*3+1], pz = pos_o[o*3+2];
        float b =      px * (W1[3*L+l] - W1[6*L+l]);
        b = fmaf(py, W1[4*L+l] - W1[7*L+l], b);
        b = fmaf(pz, W1[5*L+l] - W1[8*L+l], b);
        g_B[idx] = b;
        return;
    }
    idx -= NO * L;
    if (idx < NO * L) {
        int o = idx >> 6, l = idx & 63;
        float v = bv[l];
        #pragma unroll 8
        for (int k = 0; k < L; k++)
            v = fmaf(h_obs[o*L+k], Wv[k*L+l], v);
        g_V[idx] = v;
    }
}

// ------------------------------------------------------------------
// Main pairwise kernel. One thread = one query; block iterates over a
// CHUNK of observations staged in shared memory (pure broadcast reads).
// No max-subtraction in softmax: logits are O(1) by construction, and
// the reference result is shift-invariant, so plain exp sums are exact
// up to fp rounding. Masked pairs get weight 0 ( == exp(-inf) ).
// ------------------------------------------------------------------
__global__ void __launch_bounds__(TPB)
main_kernel(const float* __restrict__ pos_q,
            const float* __restrict__ pos_o,
            const float* __restrict__ W2,
            int NQ, int NO)
{
    __shared__ float4 Bs[CHUNK][L4];
    __shared__ float4 Vs[CHUNK][L4];
    __shared__ float  Ps[CHUNK * 3];
    __shared__ float  W2s[L];

    const int tid = threadIdx.x;
    const int o0  = blockIdx.y * CHUNK;
    const int cnt = min(CHUNK, NO - o0);

    // cooperative tile load (B, V rows for this obs chunk)
    for (int i = tid; i < cnt * L4; i += TPB) {
        int j = i / L4, c = i % L4;
        Bs[j][c] = reinterpret_cast<const float4*>(g_B)[(o0 + j) * L4 + c];
        Vs[j][c] = reinterpret_cast<const float4*>(g_V)[(o0 + j) * L4 + c];
    }
    for (int i = tid; i < cnt * 3; i += TPB)
        Ps[i] = pos_o[o0 * 3 + i];
    if (tid < L) W2s[tid] = W2[tid];
    __syncthreads();

    const int q = blockIdx.x * TPB + tid;
    if (q >= NQ) return;   // no further barriers below

    float Aq[L];
    #pragma unroll
    for (int c = 0; c < L4; c++) {
        float4 t = reinterpret_cast<const float4*>(g_A)[q * L4 + c];
        Aq[4*c+0] = t.x; Aq[4*c+1] = t.y; Aq[4*c+2] = t.z; Aq[4*c+3] = t.w;
    }
    const float qx = pos_q[q*3+0], qy = pos_q[q*3+1], qz = pos_q[q*3+2];

    float acc[L];
    #pragma unroll
    for (int l = 0; l < L; l++) acc[l] = 0.f;
    float ssum = 0.f;

    for (int j = 0; j < cnt; j++) {
        const float dx = qx - Ps[j*3+0];
        const float dy = qy - Ps[j*3+1];
        const float dz = qz - Ps[j*3+2];
        const float d2 = fmaf(dx, dx, fmaf(dy, dy, dz * dz));

        float lg0 = 0.f, lg1 = 0.f;
        #pragma unroll
        for (int c = 0; c < L4; c++) {
            const float4 b = Bs[j][c];
            float h0 = fmaxf(Aq[4*c+0] + b.x, 0.f);
            float h1 = fmaxf(Aq[4*c+1] + b.y, 0.f);
            float h2 = fmaxf(Aq[4*c+2] + b.z, 0.f);
            float h3 = fmaxf(Aq[4*c+3] + b.w, 0.f);
            lg0 = fmaf(h0, W2s[4*c+0], lg0);
            lg1 = fmaf(h1, W2s[4*c+1], lg1);
            lg0 = fmaf(h2, W2s[4*c+2], lg0);
            lg1 = fmaf(h3, W2s[4*c+3], lg1);
        }
        const float w = (d2 <= 0.25f) ? __expf(lg0 + lg1) : 0.f;
        ssum += w;
        #pragma unroll
        for (int c = 0; c < L4; c++) {
            const float4 v = Vs[j][c];
            acc[4*c+0] = fmaf(w, v.x, acc[4*c+0]);
            acc[4*c+1] = fmaf(w, v.y, acc[4*c+1]);
            acc[4*c+2] = fmaf(w, v.z, acc[4*c+2]);
            acc[4*c+3] = fmaf(w, v.w, acc[4*c+3]);
        }
    }

    // write partials for this obs chunk
    g_psum[blockIdx.y * MAXQ + q] = ssum;
    float4* pa = reinterpret_cast<float4*>(&g_pacc[((size_t)blockIdx.y * MAXQ + q) * L]);
    #pragma unroll
    for (int c = 0; c < L4; c++) {
        float4 t;
        t.x = acc[4*c+0]; t.y = acc[4*c+1]; t.z = acc[4*c+2]; t.w = acc[4*c+3];
        pa[c] = t;
    }
}

// ------------------------------------------------------------------
// Combine obs-chunk partials: out[q,l] = (sum_c acc) / (sum_c s)
// ------------------------------------------------------------------
__global__ void reduce_kernel(float* __restrict__ out, int NQ, int nch)
{
    int idx = blockIdx.x * blockDim.x + threadIdx.x;
    if (idx >= NQ * L) return;
    int q = idx >> 6;
    float s = 0.f, a = 0.f;
    for (int c = 0; c < nch; c++) {
        s += g_psum[c * MAXQ + q];
        a += g_pacc[(size_t)c * MAXQ * L + idx];
    }
    out[idx] = a / s;
}

// ------------------------------------------------------------------
extern "C" void kernel_launch(void* const* d_in, const int* in_sizes, int n_in,
                              void* d_out, int out_size)
{
    const float* h_obs     = (const float*)d_in[0];
    // d_in[1] = x_obs (unused by the reference computation)
    const float* pos_obs   = (const float*)d_in[2];
    const float* pos_query = (const float*)d_in[3];
    const float* W1        = (const float*)d_in[4];
    const float* b1        = (const float*)d_in[5];
    const float* W2        = (const float*)d_in[6];
    // d_in[7] = b2 (constant shift, cancels in softmax)
    const float* Wv        = (const float*)d_in[8];
    const float* bv        = (const float*)d_in[9];

    const int NO = in_sizes[2] / 3;
    const int NQ = in_sizes[3] / 3;

    const int total = (NQ + 2 * NO) * L;
    prep_ABV<<<(total + 255) / 256, 256>>>(pos_query, pos_obs, h_obs,
                                           W1, b1, Wv, bv, NQ, NO);

    const int nch = (NO + CHUNK - 1) / CHUNK;
    dim3 grid((NQ + TPB - 1) / TPB, nch);
    main_kernel<<<grid, TPB>>>(pos_query, pos_obs, W2, NQ, NO);

    reduce_kernel<<<(NQ * L + 255) / 256, 256>>>((float*)d_out, NQ, nch);
}

// round 6
// speedup vs baseline: 1.2554x; 1.2554x over previous
#include <cuda_runtime.h>

#define L       64
#define CHUNK   64
#define TPB     128
#define MAXQ    2048
#define MAXCH   32

typedef unsigned long long ull;

// ---- scratch ( __device__ globals: allocation-free ) ----
__device__ __align__(16) float g_A[MAXQ * L];        // per-query affine part, SORTED order
__device__ __align__(16) float g_B[MAXQ * L];        // per-obs affine part
__device__ __align__(16) float g_V[MAXQ * L];        // value-projected h_obs
__device__ float4 g_PQ[MAXQ];                        // query positions, SORTED order
__device__ int    g_perm[MAXQ];                      // sorted slot -> original query idx
__device__ float  g_psum[MAXCH * MAXQ];              // partial weight sums  (original q)
__device__ __align__(16) float g_pacc[MAXCH * MAXQ * L];  // partial value sums (original q)

// ---- packed f32x2 helpers ----
__device__ __forceinline__ ull pk_add(ull a, ull b) {
    ull r; asm("add.rn.f32x2 %0,%1,%2;" : "=l"(r) : "l"(a), "l"(b)); return r;
}
__device__ __forceinline__ ull pk_fma(ull a, ull b, ull c) {
    ull r; asm("fma.rn.f32x2 %0,%1,%2,%3;" : "=l"(r) : "l"(a), "l"(b), "l"(c)); return r;
}
union PK { ull u; float2 f; };
__device__ __forceinline__ ull pack2(float x, float y) { PK p; p.f.x = x; p.f.y = y; return p.u; }
__device__ __forceinline__ float2 unpack2(ull u) { PK p; p.u = u; return p.f; }

// ------------------------------------------------------------------
// Single-block Morton counting sort of the queries (8x8x8 cells).
// Order within a cell is atomic-nondeterministic, but downstream
// results are keyed by ORIGINAL query index and each query's math is
// thread-assignment independent -> output is bitwise deterministic.
// ------------------------------------------------------------------
__global__ void sort_kernel(const float* __restrict__ pos_q, int NQ)
{
    __shared__ int cid[MAXQ];
    __shared__ int hist[512];
    __shared__ int scanA[512];
    __shared__ int scanB[512];
    const int t = threadIdx.x;                // blockDim = 512

    if (t < 512) hist[t] = 0;
    __syncthreads();

    for (int i = t; i < NQ; i += 512) {
        float x = pos_q[3*i], y = pos_q[3*i+1], z = pos_q[3*i+2];
        int xc = min(7, max(0, (int)(x * 8.f)));
        int yc = min(7, max(0, (int)(y * 8.f)));
        int zc = min(7, max(0, (int)(z * 8.f)));
        int m = 0;
        #pragma unroll
        for (int b = 0; b < 3; b++)
            m |= (((xc >> b) & 1) << (3*b)) | (((yc >> b) & 1) << (3*b + 1))
               | (((zc >> b) & 1) << (3*b + 2));
        cid[i] = m;
        atomicAdd(&hist[m], 1);
    }
    __syncthreads();

    if (t < 512) scanA[t] = hist[t];
    __syncthreads();
    int* src = scanA; int* dst = scanB;
    for (int d = 1; d < 512; d <<= 1) {
        if (t < 512) dst[t] = src[t] + ((t >= d) ? src[t - d] : 0);
        __syncthreads();
        int* tmp = src; src = dst; dst = tmp;
    }
    if (t < 512) dst[t] = src[t] - hist[t];   // exclusive offsets in dst
    __syncthreads();

    for (int i = t; i < NQ; i += 512) {
        int p = atomicAdd(&dst[cid[i]], 1);
        g_perm[p] = i;
    }
}

// ------------------------------------------------------------------
// Precompute A (sorted order, incl. b1), B, V, sorted positions.
//   A[s,l] = b1[l] + pos_q[perm[s]] . (W1[0:3]+W1[6:9])
//   B[o,l] =         pos_o[o]       . (W1[3:6]-W1[6:9])
//   V[o,l] = bv[l] + h_obs[o] @ Wv
// ------------------------------------------------------------------
__global__ void prep_ABV(const float* __restrict__ pos_q,
                         const float* __restrict__ pos_o,
                         const float* __restrict__ h_obs,
                         const float* __restrict__ W1,
                         const float* __restrict__ b1,
                         const float* __restrict__ Wv,
                         const float* __restrict__ bv,
                         int NQ, int NO)
{
    int idx = blockIdx.x * blockDim.x + threadIdx.x;
    if (idx < NQ * L) {
        int srt = idx >> 6, l = idx & 63;
        int q = g_perm[srt];
        float px = pos_q[q*3+0], py = pos_q[q*3+1], pz = pos_q[q*3+2];
        float a = b1[l];
        a = fmaf(px, W1[0*L+l] + W1[6*L+l], a);
        a = fmaf(py, W1[1*L+l] + W1[7*L+l], a);
        a = fmaf(pz, W1[2*L+l] + W1[8*L+l], a);
        g_A[idx] = a;
        if (l == 0) g_PQ[srt] = make_float4(px, py, pz, 0.f);
        return;
    }
    idx -= NQ * L;
    if (idx < NO * L) {
        int o = idx >> 6, l = idx & 63;
        float px = pos_o[o*3+0], py = pos_o[o*3+1], pz = pos_o[o*3+2];
        float b =      px * (W1[3*L+l] - W1[6*L+l]);
        b = fmaf(py, W1[4*L+l] - W1[7*L+l], b);
        b = fmaf(pz, W1[5*L+l] - W1[8*L+l], b);
        g_B[idx] = b;
        return;
    }
    idx -= NO * L;
    if (idx < NO * L) {
        int o = idx >> 6, l = idx & 63;
        const float4* h4 = reinterpret_cast<const float4*>(h_obs + o * L);
        float v0 = bv[l], v1 = 0.f, v2 = 0.f, v3 = 0.f;
        #pragma unroll
        for (int k = 0; k < 16; k++) {
            float4 h = h4[k];
            v0 = fmaf(h.x, Wv[(4*k+0)*L + l], v0);
            v1 = fmaf(h.y, Wv[(4*k+1)*L + l], v1);
            v2 = fmaf(h.z, Wv[(4*k+2)*L + l], v2);
            v3 = fmaf(h.w, Wv[(4*k+3)*L + l], v3);
        }
        g_V[idx] = (v0 + v1) + (v2 + v3);
    }
}

// ------------------------------------------------------------------
// Main pairwise kernel. One thread = one (Morton-sorted) query.
// Fully packed f32x2 math; relu(x)*w == (x+|x|)*(w/2) exactly.
// Per-obs warp-uniform skip of the heavy body when every lane of the
// (spatially local) warp is outside the radius.
// ------------------------------------------------------------------
__global__ void __launch_bounds__(TPB, 2)
main_kernel(const float* __restrict__ pos_o,
            const float* __restrict__ W2,
            int NQ, int NO)
{
    __shared__ ulonglong2 Bs[CHUNK][16];   // 64 floats/row as 16x ulonglong2
    __shared__ ulonglong2 Vs[CHUNK][16];
    __shared__ ulonglong2 W2s[16];         // packed 0.5*W2
    __shared__ float      Ps[CHUNK * 3];

    const int tid = threadIdx.x;
    const int o0  = blockIdx.y * CHUNK;
    const int cnt = min(CHUNK, NO - o0);

    for (int i = tid; i < cnt * 16; i += TPB) {
        int j = i >> 4, c = i & 15;
        Bs[j][c] = reinterpret_cast<const ulonglong2*>(g_B)[(o0 + j) * 16 + c];
        Vs[j][c] = reinterpret_cast<const ulonglong2*>(g_V)[(o0 + j) * 16 + c];
    }
    for (int i = tid; i < cnt * 3; i += TPB)
        Ps[i] = pos_o[o0 * 3 + i];
    if (tid < 32)
        reinterpret_cast<ull*>(W2s)[tid] = pack2(0.5f * W2[2*tid], 0.5f * W2[2*tid + 1]);
    __syncthreads();

    int srt = blockIdx.x * TPB + tid;
    if (srt >= NQ) srt = NQ - 1;           // keep full warps for ballot; dup write is benign
    const int q = g_perm[srt];
    const float4 pq = g_PQ[srt];

    ull Aq[32];
    #pragma unroll
    for (int c = 0; c < 16; c++) {
        ulonglong2 t = reinterpret_cast<const ulonglong2*>(g_A)[srt * 16 + c];
        Aq[2*c] = t.x; Aq[2*c+1] = t.y;
    }
    ull acc[32];
    #pragma unroll
    for (int c = 0; c < 32; c++) acc[c] = 0ull;
    float ssum = 0.f;

    const ull ABSM = 0x7FFFFFFF7FFFFFFFull;

    for (int j = 0; j < cnt; j++) {
        const float dx = pq.x - Ps[3*j+0];
        const float dy = pq.y - Ps[3*j+1];
        const float dz = pq.z - Ps[3*j+2];
        const float d2 = fmaf(dx, dx, fmaf(dy, dy, dz * dz));
        if (__all_sync(0xFFFFFFFFu, d2 > 0.25f)) continue;

        ull lg0 = 0ull, lg1 = 0ull;
        #pragma unroll
        for (int c = 0; c < 16; c++) {
            const ulonglong2 b = Bs[j][c];
            const ulonglong2 w = W2s[c];
            ull x0 = pk_add(Aq[2*c],   b.x);
            ull x1 = pk_add(Aq[2*c+1], b.y);
            ull r0 = pk_add(x0, x0 & ABSM);     // 2*relu(x)
            ull r1 = pk_add(x1, x1 & ABSM);
            lg0 = pk_fma(r0, w.x, lg0);
            lg1 = pk_fma(r1, w.y, lg1);
        }
        float2 s0 = unpack2(lg0), s1 = unpack2(lg1);
        const float lg = (s0.x + s0.y) + (s1.x + s1.y);
        const float wgt = (d2 <= 0.25f) ? __expf(lg) : 0.f;
        ssum += wgt;
        const ull wp = pack2(wgt, wgt);
        #pragma unroll
        for (int c = 0; c < 16; c++) {
            const ulonglong2 v = Vs[j][c];
            acc[2*c]   = pk_fma(wp, v.x, acc[2*c]);
            acc[2*c+1] = pk_fma(wp, v.y, acc[2*c+1]);
        }
    }

    // partials keyed by ORIGINAL query index (deterministic output)
    g_psum[blockIdx.y * MAXQ + q] = ssum;
    float4* pa = reinterpret_cast<float4*>(&g_pacc[((size_t)blockIdx.y * MAXQ + q) * L]);
    #pragma unroll
    for (int c = 0; c < 16; c++) {
        float2 a = unpack2(acc[2*c]), b = unpack2(acc[2*c+1]);
        pa[c] = make_float4(a.x, a.y, b.x, b.y);
    }
}

// ------------------------------------------------------------------
// Combine obs-chunk partials: out[q,l] = (sum_c acc) / (sum_c s)
// ------------------------------------------------------------------
__global__ void reduce_kernel(float* __restrict__ out, int NQ, int nch)
{
    int idx = blockIdx.x * blockDim.x + threadIdx.x;
    if (idx >= NQ * L) return;
    int q = idx >> 6;
    float s = 0.f, a = 0.f;
    for (int c = 0; c < nch; c++) {
        s += g_psum[c * MAXQ + q];
        a += g_pacc[(size_t)c * MAXQ * L + idx];
    }
    out[idx] = a / s;
}

// ------------------------------------------------------------------
extern "C" void kernel_launch(void* const* d_in, const int* in_sizes, int n_in,
                              void* d_out, int out_size)
{
    const float* h_obs     = (const float*)d_in[0];
    // d_in[1] = x_obs (unused by the reference computation)
    const float* pos_obs   = (const float*)d_in[2];
    const float* pos_query = (const float*)d_in[3];
    const float* W1        = (const float*)d_in[4];
    const float* b1        = (const float*)d_in[5];
    const float* W2        = (const float*)d_in[6];
    // d_in[7] = b2 (constant shift, cancels in softmax)
    const float* Wv        = (const float*)d_in[8];
    const float* bv        = (const float*)d_in[9];

    const int NO = in_sizes[2] / 3;
    const int NQ = in_sizes[3] / 3;

    sort_kernel<<<1, 512>>>(pos_query, NQ);

    const int total = (NQ + 2 * NO) * L;
    prep_ABV<<<(total + 255) / 256, 256>>>(pos_query, pos_obs, h_obs,
                                           W1, b1, Wv, bv, NQ, NO);

    const int nch = (NO + CHUNK - 1) / CHUNK;
    dim3 grid((NQ + TPB - 1) / TPB, nch);
    main_kernel<<<grid, TPB>>>(pos_obs, W2, NQ, NO);

    reduce_kernel<<<(NQ * L + 255) / 256, 256>>>((float*)d_out, NQ, nch);
}